// round 5
// baseline (speedup 1.0000x reference)
#include <cuda_runtime.h>
#include <cstdint>
#include <math.h>

// ============================ problem constants ============================
#define NPTS 131072          // B*N = 1024*128
#define NEDG 524288          // NPTS * K(=4)

// Concat buffer layout (all segment starts 16B-aligned; pads never written => 0)
#define F_OFS  0             // features: cols 0..4   (pads 5..7)
#define O1_OFS 8             // out1:     cols 8..71
#define O2_OFS 72            // out2:     cols 72..199
#define O3_OFS 200           // out3:     cols 200..455
#define XLD    456           // 456*4 bytes = 1824 = 16*114 -> rows aligned

// ============================ device scratch ===============================
__device__ float g_X453[(size_t)NPTS * XLD];   // padded concat buffer
__device__ float g_PQ[(size_t)NPTS * 384];     // P|Q buffer (max 384 cols); reused as H2 (ld 228)
__device__ float g_H1[(size_t)NPTS * 456];     // head intermediate (ld 456, cols 453..455 stay 0)
__device__ int   g_idx[NPTS * 4];              // knn neighbor global row indices
__device__ float g_Wt[512 * 480];              // transposed weights Wt[n][kpad]

__device__ __forceinline__ float eluf(float x) { return x > 0.f ? x : expm1f(x); }

// ============================ small helpers ================================
__device__ __forceinline__ void sp_tf32(float a, float& h, float& l) {
    uint32_t hu;
    asm("cvt.rna.tf32.f32 %0, %1;" : "=r"(hu) : "f"(a));
    h = __uint_as_float(hu);
    float lf = a - h;
    uint32_t lu;
    asm("cvt.rna.tf32.f32 %0, %1;" : "=r"(lu) : "f"(lf));
    l = __uint_as_float(lu);
}
__device__ __forceinline__ void mma8(float* c, const uint32_t* a, const uint32_t* b) {
    asm volatile("mma.sync.aligned.m16n8k8.row.col.f32.tf32.tf32.f32 "
                 "{%0,%1,%2,%3}, {%4,%5,%6,%7}, {%8,%9}, {%0,%1,%2,%3};"
                 : "+f"(c[0]), "+f"(c[1]), "+f"(c[2]), "+f"(c[3])
                 : "r"(a[0]), "r"(a[1]), "r"(a[2]), "r"(a[3]), "r"(b[0]), "r"(b[1]));
}

// ============================ elementwise helpers ==========================
__global__ void copy_features_k(const float* __restrict__ f, float* __restrict__ X) {
    int e = blockIdx.x * blockDim.x + threadIdx.x;
    if (e < NPTS * 5) {
        int r = e / 5, c = e % 5;
        X[(size_t)r * XLD + c] = f[e];
    }
}
// w1[2C,H] -> Wt rows: n<H: w1_top - w1_bot ; n>=H: w1_bot   (cols k padded to Kpad)
__global__ void prep_pq_k(const float* __restrict__ w1, float* __restrict__ wt, int C, int H, int Kpad) {
    int e = blockIdx.x * blockDim.x + threadIdx.x;
    if (e >= 2 * H * Kpad) return;
    int n = e / Kpad, k = e % Kpad;
    float v = 0.f;
    if (k < C) v = (n < H) ? (w1[k * H + n] - w1[(C + k) * H + n]) : w1[(C + k) * H + (n - H)];
    wt[(size_t)n * Kpad + k] = v;
}
// w[K,N] -> Wt[n][kpad]
__global__ void prep_wt_k(const float* __restrict__ w, float* __restrict__ wt, int K, int N, int Kpad) {
    int e = blockIdx.x * blockDim.x + threadIdx.x;
    if (e >= N * Kpad) return;
    int n = e / Kpad, k = e % Kpad;
    wt[(size_t)n * Kpad + k] = (k < K) ? w[(size_t)k * N + n] : 0.f;
}
// head-1 weights: w[453,N] against PADDED concat k-layout (456 cols), Kpad=480.
__global__ void prep_head_k(const float* __restrict__ w, float* __restrict__ wt, int N, int Kpad) {
    int e = blockIdx.x * blockDim.x + threadIdx.x;
    if (e >= N * Kpad) return;
    int n = e / Kpad, kp = e % Kpad;
    float v = 0.f;
    if (kp < 5)                   v = w[(size_t)kp * N + n];
    else if (kp >= 8 && kp < 456) v = w[(size_t)(kp - 3) * N + n];
    wt[(size_t)n * Kpad + kp] = v;
}

// ============================ KNN (k=4, per-batch block) ===================
template<int C, int CP>
__global__ void __launch_bounds__(128) knn_k(const float* __restrict__ x, int ld, int cofs,
                                             int* __restrict__ idxout) {
    constexpr int PAD = CP + 4;
    __shared__ __align__(16) float sx[32][PAD];
    __shared__ float sn[128];
    int b = blockIdx.x;
    int tid = threadIdx.x;
    const float* xb = x + (size_t)b * 128 * ld + cofs;
    float4 xi[CP / 4];

    for (int t = 0; t < 4; t++) {
        for (int e = tid; e < 32 * CP; e += 128) {
            int r = e / CP, c = e % CP;
            sx[r][c] = (c < C) ? xb[(size_t)(t * 32 + r) * ld + c] : 0.f;
        }
        __syncthreads();
        if ((tid >> 5) == t) {
            int r = tid & 31;
            #pragma unroll
            for (int c4 = 0; c4 < CP / 4; c4++) xi[c4] = *(const float4*)&sx[r][4 * c4];
        }
        __syncthreads();
    }
    float ni = 0.f;
    #pragma unroll
    for (int c4 = 0; c4 < CP / 4; c4++)
        ni += xi[c4].x * xi[c4].x + xi[c4].y * xi[c4].y + xi[c4].z * xi[c4].z + xi[c4].w * xi[c4].w;
    sn[tid] = ni;
    __syncthreads();

    float bd0 = 1e30f, bd1 = 1e30f, bd2 = 1e30f, bd3 = 1e30f;
    int   bi0 = 0,     bi1 = 0,     bi2 = 0,     bi3 = 0;

    for (int t = 0; t < 4; t++) {
        for (int e = tid; e < 32 * CP; e += 128) {
            int r = e / CP, c = e % CP;
            sx[r][c] = (c < C) ? xb[(size_t)(t * 32 + r) * ld + c] : 0.f;
        }
        __syncthreads();
        for (int jl = 0; jl < 32; jl++) {
            int j = t * 32 + jl;
            float dot = 0.f;
            #pragma unroll
            for (int c4 = 0; c4 < CP / 4; c4++) {
                float4 xj = *(const float4*)&sx[jl][4 * c4];
                dot += xi[c4].x * xj.x + xi[c4].y * xj.y + xi[c4].z * xj.z + xi[c4].w * xj.w;
            }
            float d = ni + sn[j] - 2.f * dot;
            if (j == tid) d = 1e30f;
            if (d < bd3) {
                if (d < bd2) {
                    bd3 = bd2; bi3 = bi2;
                    if (d < bd1) {
                        bd2 = bd1; bi2 = bi1;
                        if (d < bd0) { bd1 = bd0; bi1 = bi0; bd0 = d; bi0 = j; }
                        else         { bd1 = d; bi1 = j; }
                    } else { bd2 = d; bi2 = j; }
                } else { bd3 = d; bi3 = j; }
            }
        }
        __syncthreads();
    }
    int base = (b * 128 + tid) * 4;
    int gb = b * 128;
    idxout[base + 0] = gb + bi0;
    idxout[base + 1] = gb + bi1;
    idxout[base + 2] = gb + bi2;
    idxout[base + 3] = gb + bi3;
}

// ============================ mma.sync tf32 GEMM ===========================
// CTA tile 128(M) x 64(N) x 32(K); 256 thr = 8 warps (4m x 2n); warp 32x32.
// tf32 hi/lo planes precomputed in SMEM at store time (split once per element).
// Register-staged double buffer: LDG next -> sync -> mma cur -> split+STS next.
#define AP 36
#define AHL (128 * AP)          // A plane floats (4608)
#define BHL (64 * AP)           // B plane floats (2304)
#define SFL (2 * AHL + 2 * BHL) // stage floats  (13824)
template<int GATHER, int ACT, int RED>
__global__ void __launch_bounds__(256, 2) mmagemm_k(
    const float* __restrict__ A, int lda, int Kval,
    const float* __restrict__ PQ, int ldpq, int qofs,
    const float* __restrict__ b1, const int* __restrict__ eidx,
    const float* __restrict__ Wt, int Kpad,
    const float* __restrict__ bias,
    float* __restrict__ Co, int ldc, int cofs, int Nfull)
{
    extern __shared__ float sm[];
    const int tid = threadIdx.x;
    const int wid = tid >> 5, lane = tid & 31;
    const int g = lane >> 2, q = lane & 3;
    const int warp_m = wid >> 1, warp_n = wid & 1;
    const int m0 = blockIdx.x * 128;
    const int n0 = blockIdx.y * 64;
    const int iters = Kpad >> 5;

    // loader thread mapping
    const int lm = tid >> 3, lkc = (tid & 7) << 2;   // dense A/B: row lm(+32i), cols lkc..lkc+3
    const int lr = tid >> 1, lh = (tid & 1) << 4;    // gather A: row lr, cols lh..lh+15

    const float *Pp = nullptr, *Qp = nullptr;
    if (GATHER) {
        int mg = m0 + lr;
        Pp = PQ + (size_t)(mg >> 2) * ldpq;
        Qp = PQ + (size_t)eidx[mg] * ldpq + qofs;
    }

    float4 rA[4], rQ[4], rB[2];

    auto ldg_tile = [&](int it) {
        const int k0 = it << 5;
        if (GATHER) {
            #pragma unroll
            for (int qq = 0; qq < 4; qq++) {
                int kk = k0 + lh + (qq << 2);
                rA[qq] = *(const float4*)(Pp + kk);
                rQ[qq] = *(const float4*)(Qp + kk);
            }
        } else {
            #pragma unroll
            for (int i = 0; i < 4; i++) {
                int gk = k0 + lkc;
                const float* src = A + (size_t)(m0 + lm + i * 32) * lda + gk;
                if (gk + 3 < Kval) {
                    rA[i] = *(const float4*)src;
                } else {
                    rA[i] = make_float4(0.f, 0.f, 0.f, 0.f);
                    if (gk + 0 < Kval) rA[i].x = src[0];
                    if (gk + 1 < Kval) rA[i].y = src[1];
                    if (gk + 2 < Kval) rA[i].z = src[2];
                }
            }
        }
        #pragma unroll
        for (int i = 0; i < 2; i++) {
            int gn = n0 + lm + i * 32;
            if (gn < Nfull) rB[i] = *(const float4*)(Wt + (size_t)gn * Kpad + (it << 5) + lkc);
            else            rB[i] = make_float4(0.f, 0.f, 0.f, 0.f);
        }
    };

    auto sts_tile = [&](int s, int it) {
        float* Ah = sm + s * SFL;
        float* Al = Ah + AHL;
        float* Bh = sm + s * SFL + 2 * AHL;
        float* Bl = Bh + BHL;
        if (GATHER) {
            const int k0 = it << 5;
            #pragma unroll
            for (int qq = 0; qq < 4; qq++) {
                int kk = lh + (qq << 2);
                float4 bv = *(const float4*)(b1 + k0 + kk);
                float4 hv, lv;
                sp_tf32(eluf(rA[qq].x + rQ[qq].x + bv.x), hv.x, lv.x);
                sp_tf32(eluf(rA[qq].y + rQ[qq].y + bv.y), hv.y, lv.y);
                sp_tf32(eluf(rA[qq].z + rQ[qq].z + bv.z), hv.z, lv.z);
                sp_tf32(eluf(rA[qq].w + rQ[qq].w + bv.w), hv.w, lv.w);
                *(float4*)&Ah[lr * AP + kk] = hv;
                *(float4*)&Al[lr * AP + kk] = lv;
            }
        } else {
            #pragma unroll
            for (int i = 0; i < 4; i++) {
                float4 hv, lv;
                sp_tf32(rA[i].x, hv.x, lv.x);
                sp_tf32(rA[i].y, hv.y, lv.y);
                sp_tf32(rA[i].z, hv.z, lv.z);
                sp_tf32(rA[i].w, hv.w, lv.w);
                *(float4*)&Ah[(lm + i * 32) * AP + lkc] = hv;
                *(float4*)&Al[(lm + i * 32) * AP + lkc] = lv;
            }
        }
        #pragma unroll
        for (int i = 0; i < 2; i++) {
            float4 hv, lv;
            sp_tf32(rB[i].x, hv.x, lv.x);
            sp_tf32(rB[i].y, hv.y, lv.y);
            sp_tf32(rB[i].z, hv.z, lv.z);
            sp_tf32(rB[i].w, hv.w, lv.w);
            *(float4*)&Bh[(lm + i * 32) * AP + lkc] = hv;
            *(float4*)&Bl[(lm + i * 32) * AP + lkc] = lv;
        }
    };

    float acc[2][4][4];
    #pragma unroll
    for (int mt = 0; mt < 2; mt++)
        #pragma unroll
        for (int nt = 0; nt < 4; nt++)
            #pragma unroll
            for (int i = 0; i < 4; i++) acc[mt][nt][i] = 0.f;

    const int abase = (warp_m * 32 + g) * AP;
    const int bbase = (warp_n * 32 + g) * AP;

    ldg_tile(0);
    sts_tile(0, 0);
    for (int it = 0; it < iters; it++) {
        if (it + 1 < iters) ldg_tile(it + 1);
        __syncthreads();
        const int s = it & 1;
        const float* Ah = sm + s * SFL;
        const float* Al = Ah + AHL;
        const float* Bh = sm + s * SFL + 2 * AHL;
        const float* Bl = Bh + BHL;
        #pragma unroll
        for (int ks = 0; ks < 4; ks++) {
            const int kb = (ks << 3) + q;
            uint32_t ah[2][4], al[2][4];
            #pragma unroll
            for (int mt = 0; mt < 2; mt++) {
                int rb = abase + mt * 16 * AP;
                ah[mt][0] = __float_as_uint(Ah[rb + kb]);
                al[mt][0] = __float_as_uint(Al[rb + kb]);
                ah[mt][1] = __float_as_uint(Ah[rb + 8 * AP + kb]);
                al[mt][1] = __float_as_uint(Al[rb + 8 * AP + kb]);
                ah[mt][2] = __float_as_uint(Ah[rb + kb + 4]);
                al[mt][2] = __float_as_uint(Al[rb + kb + 4]);
                ah[mt][3] = __float_as_uint(Ah[rb + 8 * AP + kb + 4]);
                al[mt][3] = __float_as_uint(Al[rb + 8 * AP + kb + 4]);
            }
            uint32_t bh[4][2], bl[4][2];
            #pragma unroll
            for (int nt = 0; nt < 4; nt++) {
                int rb = bbase + nt * 8 * AP;
                bh[nt][0] = __float_as_uint(Bh[rb + kb]);
                bl[nt][0] = __float_as_uint(Bl[rb + kb]);
                bh[nt][1] = __float_as_uint(Bh[rb + kb + 4]);
                bl[nt][1] = __float_as_uint(Bl[rb + kb + 4]);
            }
            #pragma unroll
            for (int mt = 0; mt < 2; mt++)
                #pragma unroll
                for (int nt = 0; nt < 4; nt++) {
                    mma8(acc[mt][nt], ah[mt], bh[nt]);
                    mma8(acc[mt][nt], al[mt], bh[nt]);
                    mma8(acc[mt][nt], ah[mt], bl[nt]);
                }
        }
        if (it + 1 < iters) sts_tile((it + 1) & 1, it + 1);
    }

    // ---- epilogue ----
    #pragma unroll
    for (int mt = 0; mt < 2; mt++) {
        const int rbase = m0 + warp_m * 32 + mt * 16;
        #pragma unroll
        for (int nt = 0; nt < 4; nt++) {
            const int cl = warp_n * 32 + nt * 8 + 2 * q;
            const int gc = n0 + cl;
            float bb0 = 0.f, bb1 = 0.f;
            if (bias != nullptr) {
                if (gc < Nfull)     bb0 = bias[gc];
                if (gc + 1 < Nfull) bb1 = bias[gc + 1];
            }
            if (!RED) {
                float v0 = acc[mt][nt][0] + bb0, v1 = acc[mt][nt][1] + bb1;
                float v2 = acc[mt][nt][2] + bb0, v3 = acc[mt][nt][3] + bb1;
                if (ACT) { v0 = eluf(v0); v1 = eluf(v1); v2 = eluf(v2); v3 = eluf(v3); }
                float* r0 = Co + (size_t)(rbase + g) * ldc + cofs;
                float* r1 = r0 + (size_t)8 * ldc;
                if (gc < Nfull)     { r0[gc] = v0;     r1[gc] = v2; }
                if (gc + 1 < Nfull) { r0[gc + 1] = v1; r1[gc + 1] = v3; }
            } else {
                #pragma unroll
                for (int half = 0; half < 2; half++) {
                    float v0 = (gc < Nfull)     ? eluf(acc[mt][nt][2 * half + 0] + bb0) : 0.f;
                    float v1 = (gc + 1 < Nfull) ? eluf(acc[mt][nt][2 * half + 1] + bb1) : 0.f;
                    v0 += __shfl_xor_sync(0xffffffffu, v0, 4);
                    v0 += __shfl_xor_sync(0xffffffffu, v0, 8);
                    v1 += __shfl_xor_sync(0xffffffffu, v1, 4);
                    v1 += __shfl_xor_sync(0xffffffffu, v1, 8);
                    if ((lane & 12) == 0) {
                        int p = (rbase + half * 8 + g) >> 2;
                        float* op = Co + (size_t)p * ldc + cofs;
                        if (gc < Nfull)     op[gc] = 0.25f * v0;
                        if (gc + 1 < Nfull) op[gc + 1] = 0.25f * v1;
                    }
                }
            }
        }
    }
}

// ============================ final tiny GEMM ==============================
__global__ void head3_k(const float* __restrict__ H2, const float* __restrict__ w,
                        const float* __restrict__ b, float* __restrict__ out) {
    int gtid = blockIdx.x * blockDim.x + threadIdx.x;
    int warp = gtid >> 5;
    int lane = threadIdx.x & 31;
    if (warp >= NPTS) return;
    const float* hr = H2 + (size_t)warp * 228;
    float a0 = 0.f, a1 = 0.f;
    for (int c = lane; c < 226; c += 32) {
        float h = hr[c];
        a0 += h * w[2 * c];
        a1 += h * w[2 * c + 1];
    }
    #pragma unroll
    for (int o = 16; o; o >>= 1) {
        a0 += __shfl_xor_sync(0xffffffffu, a0, o);
        a1 += __shfl_xor_sync(0xffffffffu, a1, o);
    }
    if (lane == 0) {
        out[2 * warp + 0] = a0 + b[0];
        out[2 * warp + 1] = a1 + b[1];
    }
}

// ============================ launcher =====================================
extern "C" void kernel_launch(void* const* d_in, const int* in_sizes, int n_in,
                              void* d_out, int out_size) {
    const float* coords   = (const float*)d_in[0];
    const float* features = (const float*)d_in[1];
    const float* c1w1 = (const float*)d_in[2];
    const float* c1b1 = (const float*)d_in[3];
    const float* c1w2 = (const float*)d_in[4];
    const float* c1b2 = (const float*)d_in[5];
    const float* c2w1 = (const float*)d_in[6];
    const float* c2b1 = (const float*)d_in[7];
    const float* c2w2 = (const float*)d_in[8];
    const float* c2b2 = (const float*)d_in[9];
    const float* c3w1 = (const float*)d_in[10];
    const float* c3b1 = (const float*)d_in[11];
    const float* c3w2 = (const float*)d_in[12];
    const float* c3b2 = (const float*)d_in[13];
    const float* ow1  = (const float*)d_in[14];
    const float* ob1  = (const float*)d_in[15];
    const float* ow2  = (const float*)d_in[16];
    const float* ob2  = (const float*)d_in[17];
    const float* ow3  = (const float*)d_in[18];
    const float* ob3  = (const float*)d_in[19];

    float *pX, *pPQ, *pH1, *pWt; int* pidx;
    cudaGetSymbolAddress((void**)&pX,  g_X453);
    cudaGetSymbolAddress((void**)&pPQ, g_PQ);
    cudaGetSymbolAddress((void**)&pH1, g_H1);
    cudaGetSymbolAddress((void**)&pWt, g_Wt);
    cudaGetSymbolAddress((void**)&pidx, g_idx);

    const int SMEM = 2 * SFL * 4;   // 110,592 B
    cudaFuncSetAttribute(mmagemm_k<0, 0, 0>, cudaFuncAttributeMaxDynamicSharedMemorySize, SMEM);
    cudaFuncSetAttribute(mmagemm_k<1, 1, 1>, cudaFuncAttributeMaxDynamicSharedMemorySize, SMEM);
    cudaFuncSetAttribute(mmagemm_k<0, 1, 0>, cudaFuncAttributeMaxDynamicSharedMemorySize, SMEM);

    const int MT_P = NPTS / 128;   // 1024
    const int MT_E = NEDG / 128;   // 4096

    copy_features_k<<<(NPTS * 5 + 255) / 256, 256>>>(features, pX);

    // ===== EdgeConv 1 (C=5, H=32, O=64) =====
    knn_k<2, 4><<<1024, 128>>>(coords, 2, 0, pidx);
    prep_pq_k<<<(64 * 32 + 255) / 256, 256>>>(c1w1, pWt, 5, 32, 32);
    mmagemm_k<0, 0, 0><<<dim3(MT_P, 1), 256, SMEM>>>(pX, XLD, 5, nullptr, 0, 0, nullptr, nullptr,
                                                     pWt, 32, nullptr, pPQ, 64, 0, 64);
    prep_wt_k<<<(64 * 32 + 255) / 256, 256>>>(c1w2, pWt, 32, 64, 32);
    mmagemm_k<1, 1, 1><<<dim3(MT_E, 1), 256, SMEM>>>(nullptr, 0, 32, pPQ, 64, 32, c1b1, pidx,
                                                     pWt, 32, c1b2, pX, XLD, O1_OFS, 64);

    // ===== EdgeConv 2 (C=64, H=96, O=128) =====
    knn_k<64, 64><<<1024, 128>>>(pX, XLD, O1_OFS, pidx);
    prep_pq_k<<<(192 * 64 + 255) / 256, 256>>>(c2w1, pWt, 64, 96, 64);
    mmagemm_k<0, 0, 0><<<dim3(MT_P, 3), 256, SMEM>>>(pX + O1_OFS, XLD, 64, nullptr, 0, 0, nullptr, nullptr,
                                                     pWt, 64, nullptr, pPQ, 192, 0, 192);
    prep_wt_k<<<(128 * 96 + 255) / 256, 256>>>(c2w2, pWt, 96, 128, 96);
    mmagemm_k<1, 1, 1><<<dim3(MT_E, 2), 256, SMEM>>>(nullptr, 0, 96, pPQ, 192, 96, c2b1, pidx,
                                                     pWt, 96, c2b2, pX, XLD, O2_OFS, 128);

    // ===== EdgeConv 3 (C=128, H=192, O=256) =====
    knn_k<128, 128><<<1024, 128>>>(pX, XLD, O2_OFS, pidx);
    prep_pq_k<<<(384 * 128 + 255) / 256, 256>>>(c3w1, pWt, 128, 192, 128);
    mmagemm_k<0, 0, 0><<<dim3(MT_P, 6), 256, SMEM>>>(pX + O2_OFS, XLD, 128, nullptr, 0, 0, nullptr, nullptr,
                                                     pWt, 128, nullptr, pPQ, 384, 0, 384);
    prep_wt_k<<<(256 * 192 + 255) / 256, 256>>>(c3w2, pWt, 192, 256, 192);
    mmagemm_k<1, 1, 1><<<dim3(MT_E, 4), 256, SMEM>>>(nullptr, 0, 192, pPQ, 384, 192, c3b1, pidx,
                                                     pWt, 192, c3b2, pX, XLD, O3_OFS, 256);

    // ===== Head =====
    prep_head_k<<<(453 * 480 + 255) / 256, 256>>>(ow1, pWt, 453, 480);
    mmagemm_k<0, 1, 0><<<dim3(MT_P, 8), 256, SMEM>>>(pX, XLD, 456, nullptr, 0, 0, nullptr, nullptr,
                                                     pWt, 480, ob1, pH1, 456, 0, 453);
    prep_wt_k<<<(226 * 480 + 255) / 256, 256>>>(ow2, pWt, 453, 226, 480);
    mmagemm_k<0, 1, 0><<<dim3(MT_P, 4), 256, SMEM>>>(pH1, 456, 456, nullptr, 0, 0, nullptr, nullptr,
                                                     pWt, 480, ob2, pPQ, 228, 0, 226);
    head3_k<<<(NPTS * 32) / 256, 256>>>(pPQ, ow3, ob3, (float*)d_out);
}

// round 6
// speedup vs baseline: 1.0912x; 1.0912x over previous
#include <cuda_runtime.h>
#include <cstdint>
#include <math.h>

// ============================ problem constants ============================
#define NPTS 131072          // B*N = 1024*128
#define NEDG 524288          // NPTS * K(=4)

// Concat buffer layout (all segment starts 16B-aligned; pads never written => 0)
#define F_OFS  0             // features: cols 0..4   (pads 5..7)
#define O1_OFS 8             // out1:     cols 8..71
#define O2_OFS 72            // out2:     cols 72..199
#define O3_OFS 200           // out3:     cols 200..455
#define XLD    456           // 456*4 bytes = 1824 = 16*114 -> rows aligned

// ============================ device scratch ===============================
__device__ float g_X453[(size_t)NPTS * XLD];   // padded concat buffer
__device__ float g_PQ[(size_t)NPTS * 384];     // P|Q buffer (max 384 cols); reused as H2 (ld 228)
__device__ float g_H1[(size_t)NPTS * 456];     // head intermediate (ld 456, cols 453..455 stay 0)
__device__ int   g_idx[NPTS * 4];              // knn neighbor global row indices
__device__ float g_Wt[512 * 480];              // transposed weights Wt[n][kpad]

__device__ __forceinline__ float eluf(float x) { return x > 0.f ? x : expm1f(x); }

// ============================ small helpers ================================
__device__ __forceinline__ void sp_tf32(float a, float& h, float& l) {
    uint32_t hu;
    asm("cvt.rna.tf32.f32 %0, %1;" : "=r"(hu) : "f"(a));
    h = __uint_as_float(hu);
    float lf = a - h;
    uint32_t lu;
    asm("cvt.rna.tf32.f32 %0, %1;" : "=r"(lu) : "f"(lf));
    l = __uint_as_float(lu);
}
__device__ __forceinline__ float rnd_tf32(float a) {
    uint32_t hu;
    asm("cvt.rna.tf32.f32 %0, %1;" : "=r"(hu) : "f"(a));
    return __uint_as_float(hu);
}
__device__ __forceinline__ void mma8(float* c, const uint32_t* a, const uint32_t* b) {
    asm volatile("mma.sync.aligned.m16n8k8.row.col.f32.tf32.tf32.f32 "
                 "{%0,%1,%2,%3}, {%4,%5,%6,%7}, {%8,%9}, {%0,%1,%2,%3};"
                 : "+f"(c[0]), "+f"(c[1]), "+f"(c[2]), "+f"(c[3])
                 : "r"(a[0]), "r"(a[1]), "r"(a[2]), "r"(a[3]), "r"(b[0]), "r"(b[1]));
}

// ============================ elementwise helpers ==========================
__global__ void copy_features_k(const float* __restrict__ f, float* __restrict__ X) {
    int e = blockIdx.x * blockDim.x + threadIdx.x;
    if (e < NPTS * 5) {
        int r = e / 5, c = e % 5;
        X[(size_t)r * XLD + c] = f[e];
    }
}
// w1[2C,H] -> Wt rows: n<H: w1_top - w1_bot ; n>=H: w1_bot   (cols k padded to Kpad)
__global__ void prep_pq_k(const float* __restrict__ w1, float* __restrict__ wt, int C, int H, int Kpad) {
    int e = blockIdx.x * blockDim.x + threadIdx.x;
    if (e >= 2 * H * Kpad) return;
    int n = e / Kpad, k = e % Kpad;
    float v = 0.f;
    if (k < C) v = (n < H) ? (w1[k * H + n] - w1[(C + k) * H + n]) : w1[(C + k) * H + (n - H)];
    wt[(size_t)n * Kpad + k] = v;
}
// w[K,N] -> Wt[n][kpad]
__global__ void prep_wt_k(const float* __restrict__ w, float* __restrict__ wt, int K, int N, int Kpad) {
    int e = blockIdx.x * blockDim.x + threadIdx.x;
    if (e >= N * Kpad) return;
    int n = e / Kpad, k = e % Kpad;
    wt[(size_t)n * Kpad + k] = (k < K) ? w[(size_t)k * N + n] : 0.f;
}
// head-1 weights: w[453,N] against PADDED concat k-layout (456 cols), Kpad=480.
__global__ void prep_head_k(const float* __restrict__ w, float* __restrict__ wt, int N, int Kpad) {
    int e = blockIdx.x * blockDim.x + threadIdx.x;
    if (e >= N * Kpad) return;
    int n = e / Kpad, kp = e % Kpad;
    float v = 0.f;
    if (kp < 5)                   v = w[(size_t)kp * N + n];
    else if (kp >= 8 && kp < 456) v = w[(size_t)(kp - 3) * N + n];
    wt[(size_t)n * Kpad + kp] = v;
}

// ============================ KNN (k=4, per-batch block) ===================
template<int C, int CP>
__global__ void __launch_bounds__(128) knn_k(const float* __restrict__ x, int ld, int cofs,
                                             int* __restrict__ idxout) {
    constexpr int PAD = CP + 4;
    __shared__ __align__(16) float sx[32][PAD];
    __shared__ float sn[128];
    int b = blockIdx.x;
    int tid = threadIdx.x;
    const float* xb = x + (size_t)b * 128 * ld + cofs;
    float4 xi[CP / 4];

    for (int t = 0; t < 4; t++) {
        for (int e = tid; e < 32 * CP; e += 128) {
            int r = e / CP, c = e % CP;
            sx[r][c] = (c < C) ? xb[(size_t)(t * 32 + r) * ld + c] : 0.f;
        }
        __syncthreads();
        if ((tid >> 5) == t) {
            int r = tid & 31;
            #pragma unroll
            for (int c4 = 0; c4 < CP / 4; c4++) xi[c4] = *(const float4*)&sx[r][4 * c4];
        }
        __syncthreads();
    }
    float ni = 0.f;
    #pragma unroll
    for (int c4 = 0; c4 < CP / 4; c4++)
        ni += xi[c4].x * xi[c4].x + xi[c4].y * xi[c4].y + xi[c4].z * xi[c4].z + xi[c4].w * xi[c4].w;
    sn[tid] = ni;
    __syncthreads();

    float bd0 = 1e30f, bd1 = 1e30f, bd2 = 1e30f, bd3 = 1e30f;
    int   bi0 = 0,     bi1 = 0,     bi2 = 0,     bi3 = 0;

    for (int t = 0; t < 4; t++) {
        for (int e = tid; e < 32 * CP; e += 128) {
            int r = e / CP, c = e % CP;
            sx[r][c] = (c < C) ? xb[(size_t)(t * 32 + r) * ld + c] : 0.f;
        }
        __syncthreads();
        for (int jl = 0; jl < 32; jl++) {
            int j = t * 32 + jl;
            float dot = 0.f;
            #pragma unroll
            for (int c4 = 0; c4 < CP / 4; c4++) {
                float4 xj = *(const float4*)&sx[jl][4 * c4];
                dot += xi[c4].x * xj.x + xi[c4].y * xj.y + xi[c4].z * xj.z + xi[c4].w * xj.w;
            }
            float d = ni + sn[j] - 2.f * dot;
            if (j == tid) d = 1e30f;
            if (d < bd3) {
                if (d < bd2) {
                    bd3 = bd2; bi3 = bi2;
                    if (d < bd1) {
                        bd2 = bd1; bi2 = bi1;
                        if (d < bd0) { bd1 = bd0; bi1 = bi0; bd0 = d; bi0 = j; }
                        else         { bd1 = d; bi1 = j; }
                    } else { bd2 = d; bi2 = j; }
                } else { bd3 = d; bi3 = j; }
            }
        }
        __syncthreads();
    }
    int base = (b * 128 + tid) * 4;
    int gb = b * 128;
    idxout[base + 0] = gb + bi0;
    idxout[base + 1] = gb + bi1;
    idxout[base + 2] = gb + bi2;
    idxout[base + 3] = gb + bi3;
}

// ============================ mma.sync tf32 GEMM ===========================
// CTA tile 128(M) x 64(N) x 32(K); 256 thr = 8 warps (4m x 2n); warp 32x32.
// tf32 hi/lo planes precomputed in SMEM at store time.
// S3=1: 3-term split (exact-ish, used where output feeds a KNN).
// S3=0: 2-term split (B tf32-rounded; 33% fewer mma; post-KNN layers only).
#define AP 36
#define AHL (128 * AP)          // A plane floats (4608)
#define BHL (64 * AP)           // B plane floats (2304)
#define SFL (2 * AHL + 2 * BHL) // stage floats  (13824)
template<int GATHER, int ACT, int RED, int S3>
__global__ void __launch_bounds__(256, 2) mmagemm_k(
    const float* __restrict__ A, int lda, int Kval,
    const float* __restrict__ PQ, int ldpq, int qofs,
    const float* __restrict__ b1, const int* __restrict__ eidx,
    const float* __restrict__ Wt, int Kpad,
    const float* __restrict__ bias,
    float* __restrict__ Co, int ldc, int cofs, int Nfull)
{
    extern __shared__ float sm[];
    const int tid = threadIdx.x;
    const int wid = tid >> 5, lane = tid & 31;
    const int g = lane >> 2, q = lane & 3;
    const int warp_m = wid >> 1, warp_n = wid & 1;
    const int m0 = blockIdx.x * 128;
    const int n0 = blockIdx.y * 64;
    const int iters = Kpad >> 5;

    // loader thread mapping
    const int lm = tid >> 3, lkc = (tid & 7) << 2;   // dense A/B: row lm(+32i), cols lkc..lkc+3
    const int lr = tid >> 1, lh = (tid & 1) << 4;    // gather A: row lr, cols lh..lh+15

    const float *Pp = nullptr, *Qp = nullptr;
    if (GATHER) {
        int mg = m0 + lr;
        Pp = PQ + (size_t)(mg >> 2) * ldpq;
        Qp = PQ + (size_t)eidx[mg] * ldpq + qofs;
    }

    float4 rA[4], rQ[4], rB[2];

    auto ldg_tile = [&](int it) {
        const int k0 = it << 5;
        if (GATHER) {
            #pragma unroll
            for (int qq = 0; qq < 4; qq++) {
                int kk = k0 + lh + (qq << 2);
                rA[qq] = *(const float4*)(Pp + kk);
                rQ[qq] = *(const float4*)(Qp + kk);
            }
        } else {
            #pragma unroll
            for (int i = 0; i < 4; i++) {
                int gk = k0 + lkc;
                const float* src = A + (size_t)(m0 + lm + i * 32) * lda + gk;
                if (gk + 3 < Kval) {
                    rA[i] = *(const float4*)src;
                } else {
                    rA[i] = make_float4(0.f, 0.f, 0.f, 0.f);
                    if (gk + 0 < Kval) rA[i].x = src[0];
                    if (gk + 1 < Kval) rA[i].y = src[1];
                    if (gk + 2 < Kval) rA[i].z = src[2];
                }
            }
        }
        #pragma unroll
        for (int i = 0; i < 2; i++) {
            int gn = n0 + lm + i * 32;
            if (gn < Nfull) rB[i] = *(const float4*)(Wt + (size_t)gn * Kpad + (it << 5) + lkc);
            else            rB[i] = make_float4(0.f, 0.f, 0.f, 0.f);
        }
    };

    auto sts_tile = [&](int s, int it) {
        float* Ah = sm + s * SFL;
        float* Al = Ah + AHL;
        float* Bh = sm + s * SFL + 2 * AHL;
        float* Bl = Bh + BHL;
        if (GATHER) {
            const int k0 = it << 5;
            #pragma unroll
            for (int qq = 0; qq < 4; qq++) {
                int kk = lh + (qq << 2);
                float4 bv = *(const float4*)(b1 + k0 + kk);
                float4 hv, lv;
                sp_tf32(eluf(rA[qq].x + rQ[qq].x + bv.x), hv.x, lv.x);
                sp_tf32(eluf(rA[qq].y + rQ[qq].y + bv.y), hv.y, lv.y);
                sp_tf32(eluf(rA[qq].z + rQ[qq].z + bv.z), hv.z, lv.z);
                sp_tf32(eluf(rA[qq].w + rQ[qq].w + bv.w), hv.w, lv.w);
                *(float4*)&Ah[lr * AP + kk] = hv;
                *(float4*)&Al[lr * AP + kk] = lv;
            }
        } else {
            #pragma unroll
            for (int i = 0; i < 4; i++) {
                float4 hv, lv;
                sp_tf32(rA[i].x, hv.x, lv.x);
                sp_tf32(rA[i].y, hv.y, lv.y);
                sp_tf32(rA[i].z, hv.z, lv.z);
                sp_tf32(rA[i].w, hv.w, lv.w);
                *(float4*)&Ah[(lm + i * 32) * AP + lkc] = hv;
                *(float4*)&Al[(lm + i * 32) * AP + lkc] = lv;
            }
        }
        #pragma unroll
        for (int i = 0; i < 2; i++) {
            if (S3) {
                float4 hv, lv;
                sp_tf32(rB[i].x, hv.x, lv.x);
                sp_tf32(rB[i].y, hv.y, lv.y);
                sp_tf32(rB[i].z, hv.z, lv.z);
                sp_tf32(rB[i].w, hv.w, lv.w);
                *(float4*)&Bh[(lm + i * 32) * AP + lkc] = hv;
                *(float4*)&Bl[(lm + i * 32) * AP + lkc] = lv;
            } else {
                float4 hv;
                hv.x = rnd_tf32(rB[i].x);
                hv.y = rnd_tf32(rB[i].y);
                hv.z = rnd_tf32(rB[i].z);
                hv.w = rnd_tf32(rB[i].w);
                *(float4*)&Bh[(lm + i * 32) * AP + lkc] = hv;
            }
        }
    };

    float acc[2][4][4];
    #pragma unroll
    for (int mt = 0; mt < 2; mt++)
        #pragma unroll
        for (int nt = 0; nt < 4; nt++)
            #pragma unroll
            for (int i = 0; i < 4; i++) acc[mt][nt][i] = 0.f;

    const int abase = (warp_m * 32 + g) * AP;
    const int bbase = (warp_n * 32 + g) * AP;

    ldg_tile(0);
    sts_tile(0, 0);
    for (int it = 0; it < iters; it++) {
        if (it + 1 < iters) ldg_tile(it + 1);
        __syncthreads();
        const int s = it & 1;
        const float* Ah = sm + s * SFL;
        const float* Al = Ah + AHL;
        const float* Bh = sm + s * SFL + 2 * AHL;
        const float* Bl = Bh + BHL;
        #pragma unroll
        for (int ks = 0; ks < 4; ks++) {
            const int kb = (ks << 3) + q;
            uint32_t ah[2][4], al[2][4];
            #pragma unroll
            for (int mt = 0; mt < 2; mt++) {
                int rb = abase + mt * 16 * AP;
                ah[mt][0] = __float_as_uint(Ah[rb + kb]);
                al[mt][0] = __float_as_uint(Al[rb + kb]);
                ah[mt][1] = __float_as_uint(Ah[rb + 8 * AP + kb]);
                al[mt][1] = __float_as_uint(Al[rb + 8 * AP + kb]);
                ah[mt][2] = __float_as_uint(Ah[rb + kb + 4]);
                al[mt][2] = __float_as_uint(Al[rb + kb + 4]);
                ah[mt][3] = __float_as_uint(Ah[rb + 8 * AP + kb + 4]);
                al[mt][3] = __float_as_uint(Al[rb + 8 * AP + kb + 4]);
            }
            uint32_t bh[4][2], bl[4][2];
            #pragma unroll
            for (int nt = 0; nt < 4; nt++) {
                int rb = bbase + nt * 8 * AP;
                bh[nt][0] = __float_as_uint(Bh[rb + kb]);
                bh[nt][1] = __float_as_uint(Bh[rb + kb + 4]);
                if (S3) {
                    bl[nt][0] = __float_as_uint(Bl[rb + kb]);
                    bl[nt][1] = __float_as_uint(Bl[rb + kb + 4]);
                }
            }
            #pragma unroll
            for (int mt = 0; mt < 2; mt++)
                #pragma unroll
                for (int nt = 0; nt < 4; nt++) {
                    mma8(acc[mt][nt], ah[mt], bh[nt]);
                    mma8(acc[mt][nt], al[mt], bh[nt]);
                    if (S3) mma8(acc[mt][nt], ah[mt], bl[nt]);
                }
        }
        if (it + 1 < iters) sts_tile((it + 1) & 1, it + 1);
    }

    // ---- epilogue ----
    #pragma unroll
    for (int mt = 0; mt < 2; mt++) {
        const int rbase = m0 + warp_m * 32 + mt * 16;
        #pragma unroll
        for (int nt = 0; nt < 4; nt++) {
            const int cl = warp_n * 32 + nt * 8 + 2 * q;
            const int gc = n0 + cl;
            float bb0 = 0.f, bb1 = 0.f;
            if (bias != nullptr) {
                if (gc < Nfull)     bb0 = bias[gc];
                if (gc + 1 < Nfull) bb1 = bias[gc + 1];
            }
            if (!RED) {
                float v0 = acc[mt][nt][0] + bb0, v1 = acc[mt][nt][1] + bb1;
                float v2 = acc[mt][nt][2] + bb0, v3 = acc[mt][nt][3] + bb1;
                if (ACT) { v0 = eluf(v0); v1 = eluf(v1); v2 = eluf(v2); v3 = eluf(v3); }
                float* r0 = Co + (size_t)(rbase + g) * ldc + cofs;
                float* r1 = r0 + (size_t)8 * ldc;
                if (gc < Nfull)     { r0[gc] = v0;     r1[gc] = v2; }
                if (gc + 1 < Nfull) { r0[gc + 1] = v1; r1[gc + 1] = v3; }
            } else {
                #pragma unroll
                for (int half = 0; half < 2; half++) {
                    float v0 = (gc < Nfull)     ? eluf(acc[mt][nt][2 * half + 0] + bb0) : 0.f;
                    float v1 = (gc + 1 < Nfull) ? eluf(acc[mt][nt][2 * half + 1] + bb1) : 0.f;
                    v0 += __shfl_xor_sync(0xffffffffu, v0, 4);
                    v0 += __shfl_xor_sync(0xffffffffu, v0, 8);
                    v1 += __shfl_xor_sync(0xffffffffu, v1, 4);
                    v1 += __shfl_xor_sync(0xffffffffu, v1, 8);
                    if ((lane & 12) == 0) {
                        int p = (rbase + half * 8 + g) >> 2;
                        float* op = Co + (size_t)p * ldc + cofs;
                        if (gc < Nfull)     op[gc] = 0.25f * v0;
                        if (gc + 1 < Nfull) op[gc + 1] = 0.25f * v1;
                    }
                }
            }
        }
    }
}

// ============================ final tiny GEMM ==============================
__global__ void head3_k(const float* __restrict__ H2, const float* __restrict__ w,
                        const float* __restrict__ b, float* __restrict__ out) {
    int gtid = blockIdx.x * blockDim.x + threadIdx.x;
    int warp = gtid >> 5;
    int lane = threadIdx.x & 31;
    if (warp >= NPTS) return;
    const float* hr = H2 + (size_t)warp * 228;
    float a0 = 0.f, a1 = 0.f;
    for (int c = lane; c < 226; c += 32) {
        float h = hr[c];
        a0 += h * w[2 * c];
        a1 += h * w[2 * c + 1];
    }
    #pragma unroll
    for (int o = 16; o; o >>= 1) {
        a0 += __shfl_xor_sync(0xffffffffu, a0, o);
        a1 += __shfl_xor_sync(0xffffffffu, a1, o);
    }
    if (lane == 0) {
        out[2 * warp + 0] = a0 + b[0];
        out[2 * warp + 1] = a1 + b[1];
    }
}

// ============================ launcher =====================================
extern "C" void kernel_launch(void* const* d_in, const int* in_sizes, int n_in,
                              void* d_out, int out_size) {
    const float* coords   = (const float*)d_in[0];
    const float* features = (const float*)d_in[1];
    const float* c1w1 = (const float*)d_in[2];
    const float* c1b1 = (const float*)d_in[3];
    const float* c1w2 = (const float*)d_in[4];
    const float* c1b2 = (const float*)d_in[5];
    const float* c2w1 = (const float*)d_in[6];
    const float* c2b1 = (const float*)d_in[7];
    const float* c2w2 = (const float*)d_in[8];
    const float* c2b2 = (const float*)d_in[9];
    const float* c3w1 = (const float*)d_in[10];
    const float* c3b1 = (const float*)d_in[11];
    const float* c3w2 = (const float*)d_in[12];
    const float* c3b2 = (const float*)d_in[13];
    const float* ow1  = (const float*)d_in[14];
    const float* ob1  = (const float*)d_in[15];
    const float* ow2  = (const float*)d_in[16];
    const float* ob2  = (const float*)d_in[17];
    const float* ow3  = (const float*)d_in[18];
    const float* ob3  = (const float*)d_in[19];

    float *pX, *pPQ, *pH1, *pWt; int* pidx;
    cudaGetSymbolAddress((void**)&pX,  g_X453);
    cudaGetSymbolAddress((void**)&pPQ, g_PQ);
    cudaGetSymbolAddress((void**)&pH1, g_H1);
    cudaGetSymbolAddress((void**)&pWt, g_Wt);
    cudaGetSymbolAddress((void**)&pidx, g_idx);

    const int SMEM = 2 * SFL * 4;   // 110,592 B
    cudaFuncSetAttribute(mmagemm_k<0, 0, 0, 1>, cudaFuncAttributeMaxDynamicSharedMemorySize, SMEM);
    cudaFuncSetAttribute(mmagemm_k<0, 0, 0, 0>, cudaFuncAttributeMaxDynamicSharedMemorySize, SMEM);
    cudaFuncSetAttribute(mmagemm_k<1, 1, 1, 1>, cudaFuncAttributeMaxDynamicSharedMemorySize, SMEM);
    cudaFuncSetAttribute(mmagemm_k<1, 1, 1, 0>, cudaFuncAttributeMaxDynamicSharedMemorySize, SMEM);
    cudaFuncSetAttribute(mmagemm_k<0, 1, 0, 0>, cudaFuncAttributeMaxDynamicSharedMemorySize, SMEM);

    const int MT_P = NPTS / 128;   // 1024
    const int MT_E = NEDG / 128;   // 4096

    copy_features_k<<<(NPTS * 5 + 255) / 256, 256>>>(features, pX);

    // ===== EdgeConv 1 (C=5, H=32, O=64) — feeds knn2: 3-term =====
    knn_k<2, 4><<<1024, 128>>>(coords, 2, 0, pidx);
    prep_pq_k<<<(64 * 32 + 255) / 256, 256>>>(c1w1, pWt, 5, 32, 32);
    mmagemm_k<0, 0, 0, 1><<<dim3(MT_P, 1), 256, SMEM>>>(pX, XLD, 5, nullptr, 0, 0, nullptr, nullptr,
                                                        pWt, 32, nullptr, pPQ, 64, 0, 64);
    prep_wt_k<<<(64 * 32 + 255) / 256, 256>>>(c1w2, pWt, 32, 64, 32);
    mmagemm_k<1, 1, 1, 1><<<dim3(MT_E, 1), 256, SMEM>>>(nullptr, 0, 32, pPQ, 64, 32, c1b1, pidx,
                                                        pWt, 32, c1b2, pX, XLD, O1_OFS, 64);

    // ===== EdgeConv 2 (C=64, H=96, O=128) — feeds knn3: 3-term =====
    knn_k<64, 64><<<1024, 128>>>(pX, XLD, O1_OFS, pidx);
    prep_pq_k<<<(192 * 64 + 255) / 256, 256>>>(c2w1, pWt, 64, 96, 64);
    mmagemm_k<0, 0, 0, 1><<<dim3(MT_P, 3), 256, SMEM>>>(pX + O1_OFS, XLD, 64, nullptr, 0, 0, nullptr, nullptr,
                                                        pWt, 64, nullptr, pPQ, 192, 0, 192);
    prep_wt_k<<<(128 * 96 + 255) / 256, 256>>>(c2w2, pWt, 96, 128, 96);
    mmagemm_k<1, 1, 1, 1><<<dim3(MT_E, 2), 256, SMEM>>>(nullptr, 0, 96, pPQ, 192, 96, c2b1, pidx,
                                                        pWt, 96, c2b2, pX, XLD, O2_OFS, 128);

    // ===== EdgeConv 3 (C=128, H=192, O=256) — post-KNN: 2-term =====
    knn_k<128, 128><<<1024, 128>>>(pX, XLD, O2_OFS, pidx);
    prep_pq_k<<<(384 * 128 + 255) / 256, 256>>>(c3w1, pWt, 128, 192, 128);
    mmagemm_k<0, 0, 0, 0><<<dim3(MT_P, 6), 256, SMEM>>>(pX + O2_OFS, XLD, 128, nullptr, 0, 0, nullptr, nullptr,
                                                        pWt, 128, nullptr, pPQ, 384, 0, 384);
    prep_wt_k<<<(256 * 192 + 255) / 256, 256>>>(c3w2, pWt, 192, 256, 192);
    mmagemm_k<1, 1, 1, 0><<<dim3(MT_E, 4), 256, SMEM>>>(nullptr, 0, 192, pPQ, 384, 192, c3b1, pidx,
                                                        pWt, 192, c3b2, pX, XLD, O3_OFS, 256);

    // ===== Head — post-KNN: 2-term =====
    prep_head_k<<<(453 * 480 + 255) / 256, 256>>>(ow1, pWt, 453, 480);
    mmagemm_k<0, 1, 0, 0><<<dim3(MT_P, 8), 256, SMEM>>>(pX, XLD, 456, nullptr, 0, 0, nullptr, nullptr,
                                                        pWt, 480, ob1, pH1, 456, 0, 453);
    prep_wt_k<<<(226 * 480 + 255) / 256, 256>>>(ow2, pWt, 453, 226, 480);
    mmagemm_k<0, 1, 0, 0><<<dim3(MT_P, 4), 256, SMEM>>>(pH1, 456, 456, nullptr, 0, 0, nullptr, nullptr,
                                                        pWt, 480, ob2, pPQ, 228, 0, 226);
    head3_k<<<(NPTS * 32) / 256, 256>>>(pPQ, ow3, ob3, (float*)d_out);
}

// round 7
// speedup vs baseline: 1.4527x; 1.3312x over previous
#include <cuda_runtime.h>
#include <cuda_bf16.h>
#include <cstdint>
#include <math.h>

// ============================ problem constants ============================
#define NPTS 131072          // B*N = 1024*128
#define NEDG 524288          // NPTS * K(=4)

// Concat buffer layout (all segment starts 16B-aligned; pads never written => 0)
#define F_OFS  0             // features: cols 0..4   (pads 5..7)
#define O1_OFS 8             // out1:     cols 8..71
#define O2_OFS 72            // out2:     cols 72..199
#define O3_OFS 200           // out3:     cols 200..455
#define XLD    456           // 456*4 bytes = 1824 = 16*114 -> rows aligned

// ============================ device scratch ===============================
__device__ float g_X453[(size_t)NPTS * XLD];   // padded concat buffer
__device__ float g_PQ[(size_t)NPTS * 384];     // P|Q buffer (max 384 cols); reused as H2 (ld 228)
__device__ float g_H1[(size_t)NPTS * 456];     // head intermediate (ld 456, cols 453..455 stay 0)
__device__ int   g_idx[NPTS * 4];              // knn neighbor global row indices
__device__ float g_Wt[512 * 480];              // transposed weights Wt[n][kpad]

__device__ __forceinline__ float eluf(float x) { return x > 0.f ? x : expm1f(x); }

// ============================ small helpers ================================
// split a pair of floats into bf16 hi/lo planes, packed (k_even low, k_odd high)
__device__ __forceinline__ void sp_bf(float a0, float a1, uint32_t& h, uint32_t& l) {
    __nv_bfloat162 hh = __floats2bfloat162_rn(a0, a1);
    float r0 = a0 - __bfloat162float(hh.x);
    float r1 = a1 - __bfloat162float(hh.y);
    __nv_bfloat162 ll = __floats2bfloat162_rn(r0, r1);
    h = *reinterpret_cast<uint32_t*>(&hh);
    l = *reinterpret_cast<uint32_t*>(&ll);
}
__device__ __forceinline__ void mma16(float* c, const uint32_t* a, const uint32_t* b) {
    asm volatile("mma.sync.aligned.m16n8k16.row.col.f32.bf16.bf16.f32 "
                 "{%0,%1,%2,%3}, {%4,%5,%6,%7}, {%8,%9}, {%0,%1,%2,%3};"
                 : "+f"(c[0]), "+f"(c[1]), "+f"(c[2]), "+f"(c[3])
                 : "r"(a[0]), "r"(a[1]), "r"(a[2]), "r"(a[3]), "r"(b[0]), "r"(b[1]));
}

// ============================ elementwise helpers ==========================
__global__ void copy_features_k(const float* __restrict__ f, float* __restrict__ X) {
    int e = blockIdx.x * blockDim.x + threadIdx.x;
    if (e < NPTS * 5) {
        int r = e / 5, c = e % 5;
        X[(size_t)r * XLD + c] = f[e];
    }
}
// w1[2C,H] -> Wt rows: n<H: w1_top - w1_bot ; n>=H: w1_bot   (cols k padded to Kpad)
__global__ void prep_pq_k(const float* __restrict__ w1, float* __restrict__ wt, int C, int H, int Kpad) {
    int e = blockIdx.x * blockDim.x + threadIdx.x;
    if (e >= 2 * H * Kpad) return;
    int n = e / Kpad, k = e % Kpad;
    float v = 0.f;
    if (k < C) v = (n < H) ? (w1[k * H + n] - w1[(C + k) * H + n]) : w1[(C + k) * H + (n - H)];
    wt[(size_t)n * Kpad + k] = v;
}
// w[K,N] -> Wt[n][kpad]
__global__ void prep_wt_k(const float* __restrict__ w, float* __restrict__ wt, int K, int N, int Kpad) {
    int e = blockIdx.x * blockDim.x + threadIdx.x;
    if (e >= N * Kpad) return;
    int n = e / Kpad, k = e % Kpad;
    wt[(size_t)n * Kpad + k] = (k < K) ? w[(size_t)k * N + n] : 0.f;
}
// head-1 weights: w[453,N] against PADDED concat k-layout (456 cols), Kpad=480.
__global__ void prep_head_k(const float* __restrict__ w, float* __restrict__ wt, int N, int Kpad) {
    int e = blockIdx.x * blockDim.x + threadIdx.x;
    if (e >= N * Kpad) return;
    int n = e / Kpad, kp = e % Kpad;
    float v = 0.f;
    if (kp < 5)                   v = w[(size_t)kp * N + n];
    else if (kp >= 8 && kp < 456) v = w[(size_t)(kp - 3) * N + n];
    wt[(size_t)n * Kpad + kp] = v;
}

// ============================ KNN (k=4, per-batch block) ===================
template<int C, int CP>
__global__ void __launch_bounds__(128) knn_k(const float* __restrict__ x, int ld, int cofs,
                                             int* __restrict__ idxout) {
    constexpr int PAD = CP + 4;
    __shared__ __align__(16) float sx[32][PAD];
    __shared__ float sn[128];
    int b = blockIdx.x;
    int tid = threadIdx.x;
    const float* xb = x + (size_t)b * 128 * ld + cofs;
    float4 xi[CP / 4];

    for (int t = 0; t < 4; t++) {
        for (int e = tid; e < 32 * CP; e += 128) {
            int r = e / CP, c = e % CP;
            sx[r][c] = (c < C) ? xb[(size_t)(t * 32 + r) * ld + c] : 0.f;
        }
        __syncthreads();
        if ((tid >> 5) == t) {
            int r = tid & 31;
            #pragma unroll
            for (int c4 = 0; c4 < CP / 4; c4++) xi[c4] = *(const float4*)&sx[r][4 * c4];
        }
        __syncthreads();
    }
    float ni = 0.f;
    #pragma unroll
    for (int c4 = 0; c4 < CP / 4; c4++)
        ni += xi[c4].x * xi[c4].x + xi[c4].y * xi[c4].y + xi[c4].z * xi[c4].z + xi[c4].w * xi[c4].w;
    sn[tid] = ni;
    __syncthreads();

    float bd0 = 1e30f, bd1 = 1e30f, bd2 = 1e30f, bd3 = 1e30f;
    int   bi0 = 0,     bi1 = 0,     bi2 = 0,     bi3 = 0;

    for (int t = 0; t < 4; t++) {
        for (int e = tid; e < 32 * CP; e += 128) {
            int r = e / CP, c = e % CP;
            sx[r][c] = (c < C) ? xb[(size_t)(t * 32 + r) * ld + c] : 0.f;
        }
        __syncthreads();
        for (int jl = 0; jl < 32; jl++) {
            int j = t * 32 + jl;
            float dot = 0.f;
            #pragma unroll
            for (int c4 = 0; c4 < CP / 4; c4++) {
                float4 xj = *(const float4*)&sx[jl][4 * c4];
                dot += xi[c4].x * xj.x + xi[c4].y * xj.y + xi[c4].z * xj.z + xi[c4].w * xj.w;
            }
            float d = ni + sn[j] - 2.f * dot;
            if (j == tid) d = 1e30f;
            if (d < bd3) {
                if (d < bd2) {
                    bd3 = bd2; bi3 = bi2;
                    if (d < bd1) {
                        bd2 = bd1; bi2 = bi1;
                        if (d < bd0) { bd1 = bd0; bi1 = bi0; bd0 = d; bi0 = j; }
                        else         { bd1 = d; bi1 = j; }
                    } else { bd2 = d; bi2 = j; }
                } else { bd3 = d; bi3 = j; }
            }
        }
        __syncthreads();
    }
    int base = (b * 128 + tid) * 4;
    int gb = b * 128;
    idxout[base + 0] = gb + bi0;
    idxout[base + 1] = gb + bi1;
    idxout[base + 2] = gb + bi2;
    idxout[base + 3] = gb + bi3;
}

// ============================ mma.sync bf16 GEMM ===========================
// CTA tile 128(M) x 64(N) x 32(K); 256 thr = 8 warps (4m x 2n); warp 32x32.
// 3-term bf16 split (ah*bh + al*bh + ah*bl), m16n8k16 -> error ~2^-18.
// SMEM planes hold packed bf16 pairs (u32 per 2 k-values), row stride 20 u32.
// Grid: x = n-tiles (fast), y = m-tiles  => co-resident blocks share A in L2.
#define APU 20                    // u32 per row (16 data + 4 pad)
#define AHLU (128 * APU)          // A plane u32s (2560)
#define BHLU (64 * APU)           // B plane u32s (1280)
#define SFLU (2 * AHLU + 2 * BHLU)// stage u32s (7680)
template<int GATHER, int ACT, int RED>
__global__ void __launch_bounds__(256, 2) mmagemm_k(
    const float* __restrict__ A, int lda, int Kval,
    const float* __restrict__ PQ, int ldpq, int qofs,
    const float* __restrict__ b1, const int* __restrict__ eidx,
    const float* __restrict__ Wt, int Kpad,
    const float* __restrict__ bias,
    float* __restrict__ Co, int ldc, int cofs, int Nfull)
{
    extern __shared__ uint32_t smu[];
    const int tid = threadIdx.x;
    const int wid = tid >> 5, lane = tid & 31;
    const int g = lane >> 2, q = lane & 3;
    const int warp_m = wid >> 1, warp_n = wid & 1;
    const int m0 = blockIdx.y * 128;
    const int n0 = blockIdx.x * 64;
    const int iters = Kpad >> 5;

    // loader thread mapping
    const int lm = tid >> 3, lkc = (tid & 7) << 2;   // dense: row lm(+32i), float cols lkc..lkc+3
    const int luc = (tid & 7) << 1;                  // dense: u32 col
    const int lr = tid >> 1, lh = (tid & 1) << 4;    // gather: row lr, float cols lh..lh+15
    const int lgu = (tid & 1) << 3;                  // gather: u32 col base

    const float *Pp = nullptr, *Qp = nullptr;
    if (GATHER) {
        int mg = m0 + lr;
        Pp = PQ + (size_t)(mg >> 2) * ldpq;
        Qp = PQ + (size_t)eidx[mg] * ldpq + qofs;
    }

    float4 rA[4], rQ[4], rB[2];

    auto ldg_tile = [&](int it) {
        const int k0 = it << 5;
        if (GATHER) {
            #pragma unroll
            for (int qq = 0; qq < 4; qq++) {
                int kk = k0 + lh + (qq << 2);
                rA[qq] = *(const float4*)(Pp + kk);
                rQ[qq] = *(const float4*)(Qp + kk);
            }
        } else {
            #pragma unroll
            for (int i = 0; i < 4; i++) {
                int gk = k0 + lkc;
                const float* src = A + (size_t)(m0 + lm + i * 32) * lda + gk;
                if (gk + 3 < Kval) {
                    rA[i] = *(const float4*)src;
                } else {
                    rA[i] = make_float4(0.f, 0.f, 0.f, 0.f);
                    if (gk + 0 < Kval) rA[i].x = src[0];
                    if (gk + 1 < Kval) rA[i].y = src[1];
                    if (gk + 2 < Kval) rA[i].z = src[2];
                }
            }
        }
        #pragma unroll
        for (int i = 0; i < 2; i++) {
            int gn = n0 + lm + i * 32;
            if (gn < Nfull) rB[i] = *(const float4*)(Wt + (size_t)gn * Kpad + (it << 5) + lkc);
            else            rB[i] = make_float4(0.f, 0.f, 0.f, 0.f);
        }
    };

    auto sts_tile = [&](int s, int it) {
        uint32_t* Ah = smu + s * SFLU;
        uint32_t* Al = Ah + AHLU;
        uint32_t* Bh = smu + s * SFLU + 2 * AHLU;
        uint32_t* Bl = Bh + BHLU;
        if (GATHER) {
            const int k0 = it << 5;
            #pragma unroll
            for (int qq = 0; qq < 4; qq++) {
                int kk = lh + (qq << 2);
                float4 bv = *(const float4*)(b1 + k0 + kk);
                float v0 = eluf(rA[qq].x + rQ[qq].x + bv.x);
                float v1 = eluf(rA[qq].y + rQ[qq].y + bv.y);
                float v2 = eluf(rA[qq].z + rQ[qq].z + bv.z);
                float v3 = eluf(rA[qq].w + rQ[qq].w + bv.w);
                uint32_t h0, l0, h1, l1;
                sp_bf(v0, v1, h0, l0);
                sp_bf(v2, v3, h1, l1);
                *(uint2*)&Ah[lr * APU + lgu + (qq << 1)] = make_uint2(h0, h1);
                *(uint2*)&Al[lr * APU + lgu + (qq << 1)] = make_uint2(l0, l1);
            }
        } else {
            #pragma unroll
            for (int i = 0; i < 4; i++) {
                uint32_t h0, l0, h1, l1;
                sp_bf(rA[i].x, rA[i].y, h0, l0);
                sp_bf(rA[i].z, rA[i].w, h1, l1);
                *(uint2*)&Ah[(lm + i * 32) * APU + luc] = make_uint2(h0, h1);
                *(uint2*)&Al[(lm + i * 32) * APU + luc] = make_uint2(l0, l1);
            }
        }
        #pragma unroll
        for (int i = 0; i < 2; i++) {
            uint32_t h0, l0, h1, l1;
            sp_bf(rB[i].x, rB[i].y, h0, l0);
            sp_bf(rB[i].z, rB[i].w, h1, l1);
            *(uint2*)&Bh[(lm + i * 32) * APU + luc] = make_uint2(h0, h1);
            *(uint2*)&Bl[(lm + i * 32) * APU + luc] = make_uint2(l0, l1);
        }
    };

    float acc[2][4][4];
    #pragma unroll
    for (int mt = 0; mt < 2; mt++)
        #pragma unroll
        for (int nt = 0; nt < 4; nt++)
            #pragma unroll
            for (int i = 0; i < 4; i++) acc[mt][nt][i] = 0.f;

    const int abase = (warp_m * 32 + g) * APU;
    const int bbase = (warp_n * 32 + g) * APU;

    ldg_tile(0);
    sts_tile(0, 0);
    for (int it = 0; it < iters; it++) {
        if (it + 1 < iters) ldg_tile(it + 1);
        __syncthreads();
        const int s = it & 1;
        const uint32_t* Ah = smu + s * SFLU;
        const uint32_t* Al = Ah + AHLU;
        const uint32_t* Bh = smu + s * SFLU + 2 * AHLU;
        const uint32_t* Bl = Bh + BHLU;
        #pragma unroll
        for (int ks = 0; ks < 2; ks++) {
            const int koff = (ks << 3) + q;
            uint32_t ah[2][4], al[2][4];
            #pragma unroll
            for (int mt = 0; mt < 2; mt++) {
                int rb = abase + mt * 16 * APU;
                ah[mt][0] = Ah[rb + koff];
                ah[mt][1] = Ah[rb + 8 * APU + koff];
                ah[mt][2] = Ah[rb + koff + 4];
                ah[mt][3] = Ah[rb + 8 * APU + koff + 4];
                al[mt][0] = Al[rb + koff];
                al[mt][1] = Al[rb + 8 * APU + koff];
                al[mt][2] = Al[rb + koff + 4];
                al[mt][3] = Al[rb + 8 * APU + koff + 4];
            }
            uint32_t bh[4][2], bl[4][2];
            #pragma unroll
            for (int nt = 0; nt < 4; nt++) {
                int rb = bbase + nt * 8 * APU;
                bh[nt][0] = Bh[rb + koff];
                bh[nt][1] = Bh[rb + koff + 4];
                bl[nt][0] = Bl[rb + koff];
                bl[nt][1] = Bl[rb + koff + 4];
            }
            #pragma unroll
            for (int mt = 0; mt < 2; mt++)
                #pragma unroll
                for (int nt = 0; nt < 4; nt++) {
                    mma16(acc[mt][nt], ah[mt], bh[nt]);
                    mma16(acc[mt][nt], al[mt], bh[nt]);
                    mma16(acc[mt][nt], ah[mt], bl[nt]);
                }
        }
        if (it + 1 < iters) sts_tile((it + 1) & 1, it + 1);
    }

    // ---- epilogue ----
    #pragma unroll
    for (int mt = 0; mt < 2; mt++) {
        const int rbase = m0 + warp_m * 32 + mt * 16;
        #pragma unroll
        for (int nt = 0; nt < 4; nt++) {
            const int cl = warp_n * 32 + nt * 8 + 2 * q;
            const int gc = n0 + cl;
            float bb0 = 0.f, bb1 = 0.f;
            if (bias != nullptr) {
                if (gc < Nfull)     bb0 = bias[gc];
                if (gc + 1 < Nfull) bb1 = bias[gc + 1];
            }
            if (!RED) {
                float v0 = acc[mt][nt][0] + bb0, v1 = acc[mt][nt][1] + bb1;
                float v2 = acc[mt][nt][2] + bb0, v3 = acc[mt][nt][3] + bb1;
                if (ACT) { v0 = eluf(v0); v1 = eluf(v1); v2 = eluf(v2); v3 = eluf(v3); }
                float* r0 = Co + (size_t)(rbase + g) * ldc + cofs;
                float* r1 = r0 + (size_t)8 * ldc;
                if (gc < Nfull)     { r0[gc] = v0;     r1[gc] = v2; }
                if (gc + 1 < Nfull) { r0[gc + 1] = v1; r1[gc + 1] = v3; }
            } else {
                #pragma unroll
                for (int half = 0; half < 2; half++) {
                    float v0 = (gc < Nfull)     ? eluf(acc[mt][nt][2 * half + 0] + bb0) : 0.f;
                    float v1 = (gc + 1 < Nfull) ? eluf(acc[mt][nt][2 * half + 1] + bb1) : 0.f;
                    v0 += __shfl_xor_sync(0xffffffffu, v0, 4);
                    v0 += __shfl_xor_sync(0xffffffffu, v0, 8);
                    v1 += __shfl_xor_sync(0xffffffffu, v1, 4);
                    v1 += __shfl_xor_sync(0xffffffffu, v1, 8);
                    if ((lane & 12) == 0) {
                        int p = (rbase + half * 8 + g) >> 2;
                        float* op = Co + (size_t)p * ldc + cofs;
                        if (gc < Nfull)     op[gc] = 0.25f * v0;
                        if (gc + 1 < Nfull) op[gc + 1] = 0.25f * v1;
                    }
                }
            }
        }
    }
}

// ============================ final tiny GEMM ==============================
__global__ void head3_k(const float* __restrict__ H2, const float* __restrict__ w,
                        const float* __restrict__ b, float* __restrict__ out) {
    int gtid = blockIdx.x * blockDim.x + threadIdx.x;
    int warp = gtid >> 5;
    int lane = threadIdx.x & 31;
    if (warp >= NPTS) return;
    const float* hr = H2 + (size_t)warp * 228;
    float a0 = 0.f, a1 = 0.f;
    for (int c = lane; c < 226; c += 32) {
        float h = hr[c];
        a0 += h * w[2 * c];
        a1 += h * w[2 * c + 1];
    }
    #pragma unroll
    for (int o = 16; o; o >>= 1) {
        a0 += __shfl_xor_sync(0xffffffffu, a0, o);
        a1 += __shfl_xor_sync(0xffffffffu, a1, o);
    }
    if (lane == 0) {
        out[2 * warp + 0] = a0 + b[0];
        out[2 * warp + 1] = a1 + b[1];
    }
}

// ============================ launcher =====================================
extern "C" void kernel_launch(void* const* d_in, const int* in_sizes, int n_in,
                              void* d_out, int out_size) {
    const float* coords   = (const float*)d_in[0];
    const float* features = (const float*)d_in[1];
    const float* c1w1 = (const float*)d_in[2];
    const float* c1b1 = (const float*)d_in[3];
    const float* c1w2 = (const float*)d_in[4];
    const float* c1b2 = (const float*)d_in[5];
    const float* c2w1 = (const float*)d_in[6];
    const float* c2b1 = (const float*)d_in[7];
    const float* c2w2 = (const float*)d_in[8];
    const float* c2b2 = (const float*)d_in[9];
    const float* c3w1 = (const float*)d_in[10];
    const float* c3b1 = (const float*)d_in[11];
    const float* c3w2 = (const float*)d_in[12];
    const float* c3b2 = (const float*)d_in[13];
    const float* ow1  = (const float*)d_in[14];
    const float* ob1  = (const float*)d_in[15];
    const float* ow2  = (const float*)d_in[16];
    const float* ob2  = (const float*)d_in[17];
    const float* ow3  = (const float*)d_in[18];
    const float* ob3  = (const float*)d_in[19];

    float *pX, *pPQ, *pH1, *pWt; int* pidx;
    cudaGetSymbolAddress((void**)&pX,  g_X453);
    cudaGetSymbolAddress((void**)&pPQ, g_PQ);
    cudaGetSymbolAddress((void**)&pH1, g_H1);
    cudaGetSymbolAddress((void**)&pWt, g_Wt);
    cudaGetSymbolAddress((void**)&pidx, g_idx);

    const int SMEM = 2 * SFLU * 4;   // 61,440 B
    cudaFuncSetAttribute(mmagemm_k<0, 0, 0>, cudaFuncAttributeMaxDynamicSharedMemorySize, SMEM);
    cudaFuncSetAttribute(mmagemm_k<1, 1, 1>, cudaFuncAttributeMaxDynamicSharedMemorySize, SMEM);
    cudaFuncSetAttribute(mmagemm_k<0, 1, 0>, cudaFuncAttributeMaxDynamicSharedMemorySize, SMEM);

    const int MT_P = NPTS / 128;   // 1024
    const int MT_E = NEDG / 128;   // 4096

    copy_features_k<<<(NPTS * 5 + 255) / 256, 256>>>(features, pX);

    // ===== EdgeConv 1 (C=5, H=32, O=64) =====
    knn_k<2, 4><<<1024, 128>>>(coords, 2, 0, pidx);
    prep_pq_k<<<(64 * 32 + 255) / 256, 256>>>(c1w1, pWt, 5, 32, 32);
    mmagemm_k<0, 0, 0><<<dim3(1, MT_P), 256, SMEM>>>(pX, XLD, 5, nullptr, 0, 0, nullptr, nullptr,
                                                     pWt, 32, nullptr, pPQ, 64, 0, 64);
    prep_wt_k<<<(64 * 32 + 255) / 256, 256>>>(c1w2, pWt, 32, 64, 32);
    mmagemm_k<1, 1, 1><<<dim3(1, MT_E), 256, SMEM>>>(nullptr, 0, 32, pPQ, 64, 32, c1b1, pidx,
                                                     pWt, 32, c1b2, pX, XLD, O1_OFS, 64);

    // ===== EdgeConv 2 (C=64, H=96, O=128) =====
    knn_k<64, 64><<<1024, 128>>>(pX, XLD, O1_OFS, pidx);
    prep_pq_k<<<(192 * 64 + 255) / 256, 256>>>(c2w1, pWt, 64, 96, 64);
    mmagemm_k<0, 0, 0><<<dim3(3, MT_P), 256, SMEM>>>(pX + O1_OFS, XLD, 64, nullptr, 0, 0, nullptr, nullptr,
                                                     pWt, 64, nullptr, pPQ, 192, 0, 192);
    prep_wt_k<<<(128 * 96 + 255) / 256, 256>>>(c2w2, pWt, 96, 128, 96);
    mmagemm_k<1, 1, 1><<<dim3(2, MT_E), 256, SMEM>>>(nullptr, 0, 96, pPQ, 192, 96, c2b1, pidx,
                                                     pWt, 96, c2b2, pX, XLD, O2_OFS, 128);

    // ===== EdgeConv 3 (C=128, H=192, O=256) =====
    knn_k<128, 128><<<1024, 128>>>(pX, XLD, O2_OFS, pidx);
    prep_pq_k<<<(384 * 128 + 255) / 256, 256>>>(c3w1, pWt, 128, 192, 128);
    mmagemm_k<0, 0, 0><<<dim3(6, MT_P), 256, SMEM>>>(pX + O2_OFS, XLD, 128, nullptr, 0, 0, nullptr, nullptr,
                                                     pWt, 128, nullptr, pPQ, 384, 0, 384);
    prep_wt_k<<<(256 * 192 + 255) / 256, 256>>>(c3w2, pWt, 192, 256, 192);
    mmagemm_k<1, 1, 1><<<dim3(4, MT_E), 256, SMEM>>>(nullptr, 0, 192, pPQ, 384, 192, c3b1, pidx,
                                                     pWt, 192, c3b2, pX, XLD, O3_OFS, 256);

    // ===== Head =====
    prep_head_k<<<(453 * 480 + 255) / 256, 256>>>(ow1, pWt, 453, 480);
    mmagemm_k<0, 1, 0><<<dim3(8, MT_P), 256, SMEM>>>(pX, XLD, 456, nullptr, 0, 0, nullptr, nullptr,
                                                     pWt, 480, ob1, pH1, 456, 0, 453);
    prep_wt_k<<<(226 * 480 + 255) / 256, 256>>>(ow2, pWt, 453, 226, 480);
    mmagemm_k<0, 1, 0><<<dim3(4, MT_P), 256, SMEM>>>(pH1, 456, 456, nullptr, 0, 0, nullptr, nullptr,
                                                     pWt, 480, ob2, pPQ, 228, 0, 226);
    head3_k<<<(NPTS * 32) / 256, 256>>>(pPQ, ow3, ob3, (float*)d_out);
}